// round 12
// baseline (speedup 1.0000x reference)
#include <cuda_runtime.h>
#include <math.h>

#define NNODES 100000
#define NEDGES 1600000
#define FIN    128
#define F1     64
#define H1N    8
#define F2     64
#define NEG_SLOPE 0.2f
#define DEGCAP 64

// ---------------- scratch (device globals; no allocation allowed) ----------------
__device__ float g_h1 [NNODES * F1];
__device__ float g_as1[NNODES * H1N];
__device__ float g_ad1[NNODES * H1N];
__device__ float g_f2 [NNODES * F1];
__device__ float g_h2 [NNODES * F2];
__device__ float g_as2[NNODES];
__device__ float g_ad2[NNODES];
__device__ int   g_cnt[NNODES];
__device__ int   g_adj[NNODES * DEGCAP];

// exp(leaky_relu(e)); lrelu(e) == max(e, 0.2*e)
__device__ __forceinline__ float pe(float e) {
    return __expf(fmaxf(e, NEG_SLOPE * e));
}

// ---------------- adjacency build ----------------
__global__ __launch_bounds__(256) void scatter_kernel(const int* __restrict__ src,
                                                      const int* __restrict__ dst) {
    int i = blockIdx.x * 256 + threadIdx.x;
    if (i >= NEDGES) return;
    int d = dst[i];
    int pos = atomicAdd(&g_cnt[d], 1);
    if (pos < DEGCAP) g_adj[d * DEGCAP + pos] = src[i];
}

// ---------------- GEMM + fused alpha epilogue ----------------
// out[N,64] = x[N,KDIM] @ W[KDIM,64]; warp ng owns nodes ng*4..ng*4+3 fully
// (lane c holds cols c and c+32), so alpha dots reduce via shuffles for free.
template<int KDIM, bool LAYER1>
__global__ __launch_bounds__(256) void gemm_kernel(const float* __restrict__ x,
                                                   const float* __restrict__ W,
                                                   float* __restrict__ out,
                                                   const float* __restrict__ a_src,
                                                   const float* __restrict__ a_dst,
                                                   float* __restrict__ as_out,
                                                   float* __restrict__ ad_out) {
    __shared__ float xs[32][KDIM];
    __shared__ float ws[KDIM][64];
    const int tid = threadIdx.x;
    const long long nbase = (long long)blockIdx.x * 32;
    const unsigned FULL = 0xffffffffu;

    for (int i = tid * 4; i < KDIM * 64; i += 256 * 4) {
        float4 v = *(const float4*)(W + i);
        *(float4*)&ws[i >> 6][i & 63] = v;
    }
    for (int i = tid * 4; i < 32 * KDIM; i += 256 * 4) {
        float4 v = *(const float4*)(x + nbase * KDIM + i);
        *(float4*)&xs[i / KDIM][i % KDIM] = v;
    }
    __syncthreads();

    const int c  = tid & 31;
    const int ng = tid >> 5;
    float acc[4][2] = {};
    #pragma unroll 8
    for (int k = 0; k < KDIM; k++) {
        float w0 = ws[k][c], w1 = ws[k][c + 32];
        #pragma unroll
        for (int i = 0; i < 4; i++) {
            float xv = xs[ng * 4 + i][k];
            acc[i][0] = fmaf(xv, w0, acc[i][0]);
            acc[i][1] = fmaf(xv, w1, acc[i][1]);
        }
    }

    const float as_lo = a_src[c], as_hi = a_src[c + 32];
    const float adc_lo = a_dst[c], adc_hi = a_dst[c + 32];

    #pragma unroll
    for (int i = 0; i < 4; i++) {
        long long n = nbase + ng * 4 + i;
        out[n * 64 + c]      = acc[i][0];
        out[n * 64 + c + 32] = acc[i][1];

        if (LAYER1) {
            // per-head dots: heads c>>3 (lo) and 4+(c>>3) (hi); 8-lane segmented reduce
            float sl = acc[i][0] * as_lo,  sh = acc[i][1] * as_hi;
            float dl = acc[i][0] * adc_lo, dh = acc[i][1] * adc_hi;
            #pragma unroll
            for (int o = 1; o < 8; o <<= 1) {
                sl += __shfl_xor_sync(FULL, sl, o);
                sh += __shfl_xor_sync(FULL, sh, o);
                dl += __shfl_xor_sync(FULL, dl, o);
                dh += __shfl_xor_sync(FULL, dh, o);
            }
            if ((c & 7) == 0) {
                int g = c >> 3;
                as_out[n * 8 + g]     = sl;
                as_out[n * 8 + 4 + g] = sh;
                ad_out[n * 8 + g]     = dl;
                ad_out[n * 8 + 4 + g] = dh;
            }
        } else {
            // full 64-col dot: full-warp reduce
            float s = acc[i][0] * as_lo  + acc[i][1] * as_hi;
            float d = acc[i][0] * adc_lo + acc[i][1] * adc_hi;
            #pragma unroll
            for (int o = 16; o > 0; o >>= 1) {
                s += __shfl_xor_sync(FULL, s, o);
                d += __shfl_xor_sync(FULL, d, o);
            }
            if (c == 0) { as_out[n] = s; ad_out[n] = d; }
        }
    }
}

// ---------------- layer-1 gather: warp per node, smem-staged (s,p), fused ELU (R8) ----------------
__global__ __launch_bounds__(256) void gather1_kernel(const float* __restrict__ b1) {
    __shared__ int   s_adj[8][DEGCAP];
    __shared__ float s_p  [8][DEGCAP * 8];

    const int warp = (blockIdx.x * 256 + threadIdx.x) >> 5;
    const int w    = (threadIdx.x >> 5);
    const int lane = threadIdx.x & 31;
    if (warp >= NNODES) return;
    const int d    = warp;
    const int head = lane >> 2;
    const int h8   = lane & 7;
    const unsigned FULL = 0xffffffffu;

    const float ad_b = g_ad1[d * 8 + h8];

    int c = g_cnt[d];
    c = c > DEGCAP ? DEGCAP : c;
    const int* row = g_adj + d * DEGCAP;
    int e0 = (lane      < c) ? row[lane]      : 0;
    int e1 = (lane + 32 < c) ? row[lane + 32] : 0;
    s_adj[w][lane]      = e0;
    s_adj[w][lane + 32] = e1;

    float accx, accy, den;
    {   // self-loop
        float ad_acc = __shfl_sync(FULL, ad_b, head);
        float as_acc = g_as1[d * 8 + head];
        float p = pe(as_acc + ad_acc);
        float2 hv = *(const float2*)(g_h1 + (long long)d * 64 + 2 * lane);
        accx = hv.x * p; accy = hv.y * p; den = p;
    }

    // stage p for all (edge, head) pairs: 4 edges per pass
    const int ngroups = (c + 3) >> 2;
    for (int g = 0; g < ngroups; g++) {
        const int j = 4 * g + (lane >> 3);
        int s = __shfl_sync(FULL, (j & 32) ? e1 : e0, j & 31);
        float p = (j < c) ? pe(g_as1[s * 8 + h8] + ad_b) : 0.f;
        s_p[w][j * 8 + h8] = p;      // 32 distinct banks
    }
    __syncwarp();

    // consume
    const float* hbase = g_h1 + 2 * lane;
    #pragma unroll 4
    for (int j = 0; j < c; j++) {
        int   sj = s_adj[w][j];              // broadcast
        float p  = s_p[w][j * 8 + head];     // 8 banks x 4-way broadcast
        float2 hv = *(const float2*)(hbase + (long long)sj * 64);
        accx = fmaf(hv.x, p, accx);
        accy = fmaf(hv.y, p, accy);
        den += p;
    }

    float inv = 1.f / (den + 1e-16f);
    float v0 = accx * inv + b1[2 * lane];
    float v1 = accy * inv + b1[2 * lane + 1];
    v0 = v0 > 0.f ? v0 : expm1f(v0);
    v1 = v1 > 0.f ? v1 : expm1f(v1);
    *(float2*)(g_f2 + (long long)d * 64 + 2 * lane) = make_float2(v0, v1);
}

// ---------------- layer-2 gather: warp per node, smem-staged (s,p), fused log_softmax (R8) ----------------
__global__ __launch_bounds__(256) void gather2_kernel(const float* __restrict__ b2,
                                                      float* __restrict__ out) {
    __shared__ uint2 s_sp[8][DEGCAP];   // (src, p) packed: one LDS.64 broadcast per edge

    const int warp = (blockIdx.x * 256 + threadIdx.x) >> 5;
    const int w    = (threadIdx.x >> 5);
    const int lane = threadIdx.x & 31;
    if (warp >= NNODES) return;
    const int d = warp;
    const unsigned FULL = 0xffffffffu;

    const float ad_d = g_ad2[d];

    int c = g_cnt[d];
    c = c > DEGCAP ? DEGCAP : c;
    const int* row = g_adj + d * DEGCAP;

    if (lane < c) {
        int e = row[lane];
        s_sp[w][lane] = make_uint2((unsigned)e, __float_as_uint(pe(g_as2[e] + ad_d)));
    }
    if (lane + 32 < c) {
        int e = row[lane + 32];
        s_sp[w][lane + 32] = make_uint2((unsigned)e, __float_as_uint(pe(g_as2[e] + ad_d)));
    }

    float accx, accy, den;
    {   // self-loop
        float p = pe(g_as2[d] + ad_d);
        float2 hv = *(const float2*)(g_h2 + (long long)d * 64 + 2 * lane);
        accx = hv.x * p; accy = hv.y * p; den = p;
    }
    __syncwarp();

    const float* hbase = g_h2 + 2 * lane;
    #pragma unroll 4
    for (int j = 0; j < c; j++) {
        uint2 sp = s_sp[w][j];               // LDS.64 broadcast
        int   sj = (int)sp.x;
        float p  = __uint_as_float(sp.y);
        float2 hv = *(const float2*)(hbase + (long long)sj * 64);
        accx = fmaf(hv.x, p, accx);
        accy = fmaf(hv.y, p, accy);
        den += p;
    }

    float inv = 1.f / (den + 1e-16f);
    float v0 = accx * inv + b2[2 * lane];
    float v1 = accy * inv + b2[2 * lane + 1];

    float mx = fmaxf(v0, v1);
    #pragma unroll
    for (int o = 16; o > 0; o >>= 1) mx = fmaxf(mx, __shfl_xor_sync(FULL, mx, o));
    float se = __expf(v0 - mx) + __expf(v1 - mx);
    #pragma unroll
    for (int o = 16; o > 0; o >>= 1) se += __shfl_xor_sync(FULL, se, o);
    float ls = mx + logf(se);

    *(float2*)(out + (long long)d * 64 + 2 * lane) = make_float2(v0 - ls, v1 - ls);
}

// ---------------- launch ----------------
extern "C" void kernel_launch(void* const* d_in, const int* in_sizes, int n_in,
                              void* d_out, int out_size) {
    const float* x      = (const float*)d_in[0];
    const int*   eidx   = (const int*)  d_in[1];
    const float* W1     = (const float*)d_in[2];
    const float* a_src1 = (const float*)d_in[3];
    const float* a_dst1 = (const float*)d_in[4];
    const float* b1     = (const float*)d_in[5];
    const float* W2     = (const float*)d_in[6];
    const float* a_src2 = (const float*)d_in[7];
    const float* a_dst2 = (const float*)d_in[8];
    const float* b2     = (const float*)d_in[9];
    float* out = (float*)d_out;

    const int* src = eidx;
    const int* dst = eidx + NEDGES;

    float *p_h1, *p_f2, *p_h2, *p_as1, *p_ad1, *p_as2, *p_ad2;
    int* p_cnt;
    cudaGetSymbolAddress((void**)&p_h1,  g_h1);
    cudaGetSymbolAddress((void**)&p_f2,  g_f2);
    cudaGetSymbolAddress((void**)&p_h2,  g_h2);
    cudaGetSymbolAddress((void**)&p_as1, g_as1);
    cudaGetSymbolAddress((void**)&p_ad1, g_ad1);
    cudaGetSymbolAddress((void**)&p_as2, g_as2);
    cudaGetSymbolAddress((void**)&p_ad2, g_ad2);
    cudaGetSymbolAddress((void**)&p_cnt, g_cnt);

    const int TB = 256;
    cudaMemsetAsync(p_cnt, 0, NNODES * sizeof(int));
    scatter_kernel<<<(NEDGES + TB - 1) / TB, TB>>>(src, dst);
    // layer 1 (alpha fused into gemm epilogue)
    gemm_kernel<FIN, true><<<NNODES / 32, TB>>>(x, W1, p_h1, a_src1, a_dst1, p_as1, p_ad1);
    gather1_kernel<<<(NNODES * 32 + TB - 1) / TB, TB>>>(b1);
    // layer 2
    gemm_kernel<F1, false><<<NNODES / 32, TB>>>(p_f2, W2, p_h2, a_src2, a_dst2, p_as2, p_ad2);
    gather2_kernel<<<(NNODES * 32 + TB - 1) / TB, TB>>>(b2, out);
}

// round 13
// speedup vs baseline: 1.4600x; 1.4600x over previous
#include <cuda_runtime.h>
#include <math.h>

#define NNODES 100000
#define NEDGES 1600000
#define FIN    128
#define F1     64
#define H1N    8
#define F2     64
#define NEG_SLOPE 0.2f
#define DEGCAP 64

// ---------------- scratch (device globals; no allocation allowed) ----------------
__device__ float g_h1 [NNODES * F1];
__device__ float g_as1[NNODES * H1N];
__device__ float g_ad1[NNODES * H1N];
__device__ float g_f2 [NNODES * F1];
__device__ float g_h2 [NNODES * F2];
__device__ float g_as2[NNODES];
__device__ float g_ad2[NNODES];
__device__ int   g_cnt[NNODES];
__device__ int   g_adj[NNODES * DEGCAP];

// exp(leaky_relu(e)); lrelu(e) == max(e, 0.2*e)
__device__ __forceinline__ float pe(float e) {
    return __expf(fmaxf(e, NEG_SLOPE * e));
}

// ---------------- adjacency build ----------------
__global__ __launch_bounds__(256) void scatter_kernel(const int* __restrict__ src,
                                                      const int* __restrict__ dst) {
    int i = blockIdx.x * 256 + threadIdx.x;
    if (i >= NEDGES) return;
    int d = dst[i];
    int pos = atomicAdd(&g_cnt[d], 1);
    if (pos < DEGCAP) g_adj[d * DEGCAP + pos] = src[i];
}

// ---------------- GEMM + smem-fused alpha epilogue ----------------
// out[N,64] = x[N,KDIM] @ W[KDIM,64]. After stores, alpha products are written
// to the (now-dead) xs/ws smem, one barrier, then reduced by re-partitioned threads.
template<int KDIM, bool LAYER1>
__global__ __launch_bounds__(256) void gemm_kernel(const float* __restrict__ x,
                                                   const float* __restrict__ W,
                                                   float* __restrict__ out,
                                                   const float* __restrict__ a_src,
                                                   const float* __restrict__ a_dst,
                                                   float* __restrict__ as_out,
                                                   float* __restrict__ ad_out) {
    __shared__ float xs[32][KDIM];   // >= 2048 floats: reused as s_as (32 nodes x 64 cols)
    __shared__ float ws[KDIM][64];   // >= 4096 floats: reused as s_ad + layer-2 partials
    const int tid = threadIdx.x;
    const long long nbase = (long long)blockIdx.x * 32;

    for (int i = tid * 4; i < KDIM * 64; i += 256 * 4) {
        float4 v = *(const float4*)(W + i);
        *(float4*)&ws[i >> 6][i & 63] = v;
    }
    for (int i = tid * 4; i < 32 * KDIM; i += 256 * 4) {
        float4 v = *(const float4*)(x + nbase * KDIM + i);
        *(float4*)&xs[i / KDIM][i % KDIM] = v;
    }
    __syncthreads();

    const int c  = tid & 31;
    const int ng = tid >> 5;
    float acc[4][2] = {};
    #pragma unroll 8
    for (int k = 0; k < KDIM; k++) {
        float w0 = ws[k][c], w1 = ws[k][c + 32];
        #pragma unroll
        for (int i = 0; i < 4; i++) {
            float xv = xs[ng * 4 + i][k];
            acc[i][0] = fmaf(xv, w0, acc[i][0]);
            acc[i][1] = fmaf(xv, w1, acc[i][1]);
        }
    }
    #pragma unroll
    for (int i = 0; i < 4; i++) {
        long long n = nbase + ng * 4 + i;
        out[n * 64 + c]      = acc[i][0];
        out[n * 64 + c + 32] = acc[i][1];
    }

    // ---- fused alpha epilogue (smem reduction; xs/ws contents are dead now) ----
    float* s_as = &xs[0][0];              // [32 nodes][64 cols]
    float* s_ad = &ws[0][0];              // [32 nodes][64 cols]
    const float aslo = a_src[c], ashi = a_src[c + 32];
    const float adlo = a_dst[c], adhi = a_dst[c + 32];
    __syncthreads();                      // everyone done reading xs/ws
    #pragma unroll
    for (int i = 0; i < 4; i++) {
        int nl = ng * 4 + i;
        s_as[nl * 64 + c]      = acc[i][0] * aslo;
        s_as[nl * 64 + c + 32] = acc[i][1] * ashi;
        s_ad[nl * 64 + c]      = acc[i][0] * adlo;
        s_ad[nl * 64 + c + 32] = acc[i][1] * adhi;
    }
    __syncthreads();

    if (LAYER1) {
        // thread <-> (node, head): sum 8-col segment
        int nl = tid >> 3, hh = tid & 7;
        float s = 0.f, d = 0.f;
        #pragma unroll
        for (int j = 0; j < 8; j++) {
            s += s_as[nl * 64 + hh * 8 + j];
            d += s_ad[nl * 64 + hh * 8 + j];
        }
        long long n = nbase + nl;
        as_out[n * 8 + hh] = s;
        ad_out[n * 8 + hh] = d;
    } else {
        // stage 1: 8 partials per node; stage 2: thread<32 finishes
        float* part = &ws[0][0] + 2048;   // [32 nodes][8 seg][2]
        int nl = tid >> 3, seg = tid & 7;
        float s = 0.f, d = 0.f;
        #pragma unroll
        for (int j = 0; j < 8; j++) {
            s += s_as[nl * 64 + seg * 8 + j];
            d += s_ad[nl * 64 + seg * 8 + j];
        }
        part[(nl * 8 + seg) * 2]     = s;
        part[(nl * 8 + seg) * 2 + 1] = d;
        __syncthreads();
        if (tid < 32) {
            float ss = 0.f, dd = 0.f;
            #pragma unroll
            for (int j = 0; j < 8; j++) {
                ss += part[(tid * 8 + j) * 2];
                dd += part[(tid * 8 + j) * 2 + 1];
            }
            long long n = nbase + tid;
            as_out[n] = ss;
            ad_out[n] = dd;
        }
    }
}

// ---------------- layer-1 gather: warp per node, smem-staged (s,p), fused ELU (R8) ----------------
__global__ __launch_bounds__(256) void gather1_kernel(const float* __restrict__ b1) {
    __shared__ int   s_adj[8][DEGCAP];
    __shared__ float s_p  [8][DEGCAP * 8];

    const int warp = (blockIdx.x * 256 + threadIdx.x) >> 5;
    const int w    = (threadIdx.x >> 5);
    const int lane = threadIdx.x & 31;
    if (warp >= NNODES) return;
    const int d    = warp;
    const int head = lane >> 2;
    const int h8   = lane & 7;
    const unsigned FULL = 0xffffffffu;

    const float ad_b = g_ad1[d * 8 + h8];

    int c = g_cnt[d];
    c = c > DEGCAP ? DEGCAP : c;
    const int* row = g_adj + d * DEGCAP;
    int e0 = (lane      < c) ? row[lane]      : 0;
    int e1 = (lane + 32 < c) ? row[lane + 32] : 0;
    s_adj[w][lane]      = e0;
    s_adj[w][lane + 32] = e1;

    float accx, accy, den;
    {   // self-loop
        float ad_acc = __shfl_sync(FULL, ad_b, head);
        float as_acc = g_as1[d * 8 + head];
        float p = pe(as_acc + ad_acc);
        float2 hv = *(const float2*)(g_h1 + (long long)d * 64 + 2 * lane);
        accx = hv.x * p; accy = hv.y * p; den = p;
    }

    // stage p for all (edge, head) pairs: 4 edges per pass
    const int ngroups = (c + 3) >> 2;
    for (int g = 0; g < ngroups; g++) {
        const int j = 4 * g + (lane >> 3);
        int s = __shfl_sync(FULL, (j & 32) ? e1 : e0, j & 31);
        float p = (j < c) ? pe(g_as1[s * 8 + h8] + ad_b) : 0.f;
        s_p[w][j * 8 + h8] = p;      // 32 distinct banks
    }
    __syncwarp();

    // consume
    const float* hbase = g_h1 + 2 * lane;
    #pragma unroll 4
    for (int j = 0; j < c; j++) {
        int   sj = s_adj[w][j];              // broadcast
        float p  = s_p[w][j * 8 + head];     // 8 banks x 4-way broadcast
        float2 hv = *(const float2*)(hbase + (long long)sj * 64);
        accx = fmaf(hv.x, p, accx);
        accy = fmaf(hv.y, p, accy);
        den += p;
    }

    float inv = 1.f / (den + 1e-16f);
    float v0 = accx * inv + b1[2 * lane];
    float v1 = accy * inv + b1[2 * lane + 1];
    v0 = v0 > 0.f ? v0 : expm1f(v0);
    v1 = v1 > 0.f ? v1 : expm1f(v1);
    *(float2*)(g_f2 + (long long)d * 64 + 2 * lane) = make_float2(v0, v1);
}

// ---------------- layer-2 gather: warp per node, smem-staged (s,p), fused log_softmax (R8) ----------------
__global__ __launch_bounds__(256) void gather2_kernel(const float* __restrict__ b2,
                                                      float* __restrict__ out) {
    __shared__ uint2 s_sp[8][DEGCAP];   // (src, p) packed: one LDS.64 broadcast per edge

    const int warp = (blockIdx.x * 256 + threadIdx.x) >> 5;
    const int w    = (threadIdx.x >> 5);
    const int lane = threadIdx.x & 31;
    if (warp >= NNODES) return;
    const int d = warp;
    const unsigned FULL = 0xffffffffu;

    const float ad_d = g_ad2[d];

    int c = g_cnt[d];
    c = c > DEGCAP ? DEGCAP : c;
    const int* row = g_adj + d * DEGCAP;

    if (lane < c) {
        int e = row[lane];
        s_sp[w][lane] = make_uint2((unsigned)e, __float_as_uint(pe(g_as2[e] + ad_d)));
    }
    if (lane + 32 < c) {
        int e = row[lane + 32];
        s_sp[w][lane + 32] = make_uint2((unsigned)e, __float_as_uint(pe(g_as2[e] + ad_d)));
    }

    float accx, accy, den;
    {   // self-loop
        float p = pe(g_as2[d] + ad_d);
        float2 hv = *(const float2*)(g_h2 + (long long)d * 64 + 2 * lane);
        accx = hv.x * p; accy = hv.y * p; den = p;
    }
    __syncwarp();

    const float* hbase = g_h2 + 2 * lane;
    #pragma unroll 4
    for (int j = 0; j < c; j++) {
        uint2 sp = s_sp[w][j];               // LDS.64 broadcast
        int   sj = (int)sp.x;
        float p  = __uint_as_float(sp.y);
        float2 hv = *(const float2*)(hbase + (long long)sj * 64);
        accx = fmaf(hv.x, p, accx);
        accy = fmaf(hv.y, p, accy);
        den += p;
    }

    float inv = 1.f / (den + 1e-16f);
    float v0 = accx * inv + b2[2 * lane];
    float v1 = accy * inv + b2[2 * lane + 1];

    float mx = fmaxf(v0, v1);
    #pragma unroll
    for (int o = 16; o > 0; o >>= 1) mx = fmaxf(mx, __shfl_xor_sync(FULL, mx, o));
    float se = __expf(v0 - mx) + __expf(v1 - mx);
    #pragma unroll
    for (int o = 16; o > 0; o >>= 1) se += __shfl_xor_sync(FULL, se, o);
    float ls = mx + logf(se);

    *(float2*)(out + (long long)d * 64 + 2 * lane) = make_float2(v0 - ls, v1 - ls);
}

// ---------------- launch ----------------
extern "C" void kernel_launch(void* const* d_in, const int* in_sizes, int n_in,
                              void* d_out, int out_size) {
    const float* x      = (const float*)d_in[0];
    const int*   eidx   = (const int*)  d_in[1];
    const float* W1     = (const float*)d_in[2];
    const float* a_src1 = (const float*)d_in[3];
    const float* a_dst1 = (const float*)d_in[4];
    const float* b1     = (const float*)d_in[5];
    const float* W2     = (const float*)d_in[6];
    const float* a_src2 = (const float*)d_in[7];
    const float* a_dst2 = (const float*)d_in[8];
    const float* b2     = (const float*)d_in[9];
    float* out = (float*)d_out;

    const int* src = eidx;
    const int* dst = eidx + NEDGES;

    float *p_h1, *p_f2, *p_h2, *p_as1, *p_ad1, *p_as2, *p_ad2;
    int* p_cnt;
    cudaGetSymbolAddress((void**)&p_h1,  g_h1);
    cudaGetSymbolAddress((void**)&p_f2,  g_f2);
    cudaGetSymbolAddress((void**)&p_h2,  g_h2);
    cudaGetSymbolAddress((void**)&p_as1, g_as1);
    cudaGetSymbolAddress((void**)&p_ad1, g_ad1);
    cudaGetSymbolAddress((void**)&p_as2, g_as2);
    cudaGetSymbolAddress((void**)&p_ad2, g_ad2);
    cudaGetSymbolAddress((void**)&p_cnt, g_cnt);

    const int TB = 256;
    cudaMemsetAsync(p_cnt, 0, NNODES * sizeof(int));
    scatter_kernel<<<(NEDGES + TB - 1) / TB, TB>>>(src, dst);
    // layer 1 (alpha fused into gemm epilogue via smem)
    gemm_kernel<FIN, true><<<NNODES / 32, TB>>>(x, W1, p_h1, a_src1, a_dst1, p_as1, p_ad1);
    gather1_kernel<<<(NNODES * 32 + TB - 1) / TB, TB>>>(b1);
    // layer 2
    gemm_kernel<F1, false><<<NNODES / 32, TB>>>(p_f2, W2, p_h2, a_src2, a_dst2, p_as2, p_ad2);
    gather2_kernel<<<(NNODES * 32 + TB - 1) / TB, TB>>>(b2, out);
}

// round 14
// speedup vs baseline: 1.4851x; 1.0172x over previous
#include <cuda_runtime.h>
#include <math.h>

#define NNODES 100000
#define NEDGES 1600000
#define FIN    128
#define F1     64
#define H1N    8
#define F2     64
#define NEG_SLOPE 0.2f
#define DEGCAP 64

// ---------------- scratch (device globals; no allocation allowed) ----------------
__device__ float g_h1 [NNODES * F1];
__device__ float g_as1[NNODES * H1N];
__device__ float g_ad1[NNODES * H1N];
__device__ float g_f2 [NNODES * F1];
__device__ float g_h2 [NNODES * F2];
__device__ float g_as2[NNODES];
__device__ float g_ad2[NNODES];
__device__ int   g_cnt[NNODES];
__device__ int   g_adj[NNODES * DEGCAP];

// exp(leaky_relu(e)); lrelu(e) == max(e, 0.2*e)
__device__ __forceinline__ float pe(float e) {
    return __expf(fmaxf(e, NEG_SLOPE * e));
}

// ---------------- adjacency build ----------------
__global__ __launch_bounds__(256) void scatter_kernel(const int* __restrict__ src,
                                                      const int* __restrict__ dst) {
    int i = blockIdx.x * 256 + threadIdx.x;
    if (i >= NEDGES) return;
    int d = dst[i];
    int pos = atomicAdd(&g_cnt[d], 1);
    if (pos < DEGCAP) g_adj[d * DEGCAP + pos] = src[i];
}

// ---------------- GEMM (4 nodes x 8 cols / thread) + fused alpha epilogue ----------------
// Block: 128 nodes x 64 cols, 256 threads. Thread (tn = tid>>3, tc = tid&7):
// nodes tn+32i (i<4), cols 8tc..8tc+7. All operand LDS are 128-bit.
template<int KDIM, bool LAYER1>
__global__ __launch_bounds__(256) void gemm_kernel(const float* __restrict__ x,
                                                   const float* __restrict__ W,
                                                   float* __restrict__ out,
                                                   const float* __restrict__ a_src,
                                                   const float* __restrict__ a_dst,
                                                   float* __restrict__ as_out,
                                                   float* __restrict__ ad_out) {
    __shared__ float xs[128][36];    // k-chunk of 32 (+4 pad), rows 144B (16B-aligned)
    __shared__ float ws[32][64];     // reused as layer-2 partials [128][8][2]
    const int tid = threadIdx.x;
    const int tc  = tid & 7;
    const int tn  = tid >> 3;
    const int nbase = blockIdx.x * 128;

    float acc[4][8] = {};

    for (int kc = 0; kc < KDIM / 32; kc++) {
        if (kc) __syncthreads();
        // W chunk: 32 x 64 = 512 float4
        #pragma unroll
        for (int f = tid; f < 512; f += 256) {
            int k = f >> 4, cq = f & 15;
            float4 v = *(const float4*)(W + (kc * 32 + k) * 64 + 4 * cq);
            *(float4*)&ws[k][4 * cq] = v;
        }
        // x chunk: 128 rows x 32 k = 1024 float4
        #pragma unroll
        for (int f = tid; f < 1024; f += 256) {
            int r = f >> 3, q = f & 7;
            int row = nbase + r;
            float4 v = make_float4(0.f, 0.f, 0.f, 0.f);
            if (row < NNODES) v = *(const float4*)(x + (long long)row * KDIM + kc * 32 + 4 * q);
            *(float4*)&xs[r][4 * q] = v;
        }
        __syncthreads();

        #pragma unroll
        for (int k4 = 0; k4 < 8; k4++) {
            float4 xv[4];
            #pragma unroll
            for (int i = 0; i < 4; i++) xv[i] = *(const float4*)&xs[tn + 32 * i][4 * k4];
            #pragma unroll
            for (int kk = 0; kk < 4; kk++) {
                float4 w0 = *(const float4*)&ws[4 * k4 + kk][8 * tc];
                float4 w1 = *(const float4*)&ws[4 * k4 + kk][8 * tc + 4];
                #pragma unroll
                for (int i = 0; i < 4; i++) {
                    float xk = ((const float*)&xv[i])[kk];
                    acc[i][0] = fmaf(xk, w0.x, acc[i][0]);
                    acc[i][1] = fmaf(xk, w0.y, acc[i][1]);
                    acc[i][2] = fmaf(xk, w0.z, acc[i][2]);
                    acc[i][3] = fmaf(xk, w0.w, acc[i][3]);
                    acc[i][4] = fmaf(xk, w1.x, acc[i][4]);
                    acc[i][5] = fmaf(xk, w1.y, acc[i][5]);
                    acc[i][6] = fmaf(xk, w1.z, acc[i][6]);
                    acc[i][7] = fmaf(xk, w1.w, acc[i][7]);
                }
            }
        }
    }

    // stores
    #pragma unroll
    for (int i = 0; i < 4; i++) {
        int n = nbase + tn + 32 * i;
        if (n < NNODES) {
            float* op = out + (long long)n * 64 + 8 * tc;
            *(float4*)(op)     = make_float4(acc[i][0], acc[i][1], acc[i][2], acc[i][3]);
            *(float4*)(op + 4) = make_float4(acc[i][4], acc[i][5], acc[i][6], acc[i][7]);
        }
    }

    // ---- fused alpha epilogue ----
    float4 asA = *(const float4*)(a_src + 8 * tc);
    float4 asB = *(const float4*)(a_src + 8 * tc + 4);
    float4 adA = *(const float4*)(a_dst + 8 * tc);
    float4 adB = *(const float4*)(a_dst + 8 * tc + 4);

    if (LAYER1) {
        // cols 8tc..8tc+7 == head tc: dot is fully thread-local
        #pragma unroll
        for (int i = 0; i < 4; i++) {
            int n = nbase + tn + 32 * i;
            float s = acc[i][0] * asA.x + acc[i][1] * asA.y + acc[i][2] * asA.z + acc[i][3] * asA.w
                    + acc[i][4] * asB.x + acc[i][5] * asB.y + acc[i][6] * asB.z + acc[i][7] * asB.w;
            float d = acc[i][0] * adA.x + acc[i][1] * adA.y + acc[i][2] * adA.z + acc[i][3] * adA.w
                    + acc[i][4] * adB.x + acc[i][5] * adB.y + acc[i][6] * adB.z + acc[i][7] * adB.w;
            if (n < NNODES) {
                as_out[n * 8 + tc] = s;
                ad_out[n * 8 + tc] = d;
            }
        }
    } else {
        // 64-col dot: 8 partials per node via smem (reuse ws: [128 nodes][8 seg][2])
        __syncthreads();
        float* part = &ws[0][0];
        #pragma unroll
        for (int i = 0; i < 4; i++) {
            int nl = tn + 32 * i;
            float s = acc[i][0] * asA.x + acc[i][1] * asA.y + acc[i][2] * asA.z + acc[i][3] * asA.w
                    + acc[i][4] * asB.x + acc[i][5] * asB.y + acc[i][6] * asB.z + acc[i][7] * asB.w;
            float d = acc[i][0] * adA.x + acc[i][1] * adA.y + acc[i][2] * adA.z + acc[i][3] * adA.w
                    + acc[i][4] * adB.x + acc[i][5] * adB.y + acc[i][6] * adB.z + acc[i][7] * adB.w;
            part[nl * 16 + tc * 2]     = s;
            part[nl * 16 + tc * 2 + 1] = d;
        }
        __syncthreads();
        if (tid < 128) {
            float ss = 0.f, dd = 0.f;
            #pragma unroll
            for (int j = 0; j < 8; j++) {
                ss += part[tid * 16 + 2 * j];
                dd += part[tid * 16 + 2 * j + 1];
            }
            int n = nbase + tid;
            if (n < NNODES) { as_out[n] = ss; ad_out[n] = dd; }
        }
    }
}

// ---------------- layer-1 gather: warp per node, smem-staged (s,p), fused ELU (R8) ----------------
__global__ __launch_bounds__(256) void gather1_kernel(const float* __restrict__ b1) {
    __shared__ int   s_adj[8][DEGCAP];
    __shared__ float s_p  [8][DEGCAP * 8];

    const int warp = (blockIdx.x * 256 + threadIdx.x) >> 5;
    const int w    = (threadIdx.x >> 5);
    const int lane = threadIdx.x & 31;
    if (warp >= NNODES) return;
    const int d    = warp;
    const int head = lane >> 2;
    const int h8   = lane & 7;
    const unsigned FULL = 0xffffffffu;

    const float ad_b = g_ad1[d * 8 + h8];

    int c = g_cnt[d];
    c = c > DEGCAP ? DEGCAP : c;
    const int* row = g_adj + d * DEGCAP;
    int e0 = (lane      < c) ? row[lane]      : 0;
    int e1 = (lane + 32 < c) ? row[lane + 32] : 0;
    s_adj[w][lane]      = e0;
    s_adj[w][lane + 32] = e1;

    float accx, accy, den;
    {   // self-loop
        float ad_acc = __shfl_sync(FULL, ad_b, head);
        float as_acc = g_as1[d * 8 + head];
        float p = pe(as_acc + ad_acc);
        float2 hv = *(const float2*)(g_h1 + (long long)d * 64 + 2 * lane);
        accx = hv.x * p; accy = hv.y * p; den = p;
    }

    // stage p for all (edge, head) pairs: 4 edges per pass
    const int ngroups = (c + 3) >> 2;
    for (int g = 0; g < ngroups; g++) {
        const int j = 4 * g + (lane >> 3);
        int s = __shfl_sync(FULL, (j & 32) ? e1 : e0, j & 31);
        float p = (j < c) ? pe(g_as1[s * 8 + h8] + ad_b) : 0.f;
        s_p[w][j * 8 + h8] = p;      // 32 distinct banks
    }
    __syncwarp();

    // consume
    const float* hbase = g_h1 + 2 * lane;
    #pragma unroll 4
    for (int j = 0; j < c; j++) {
        int   sj = s_adj[w][j];              // broadcast
        float p  = s_p[w][j * 8 + head];     // 8 banks x 4-way broadcast
        float2 hv = *(const float2*)(hbase + (long long)sj * 64);
        accx = fmaf(hv.x, p, accx);
        accy = fmaf(hv.y, p, accy);
        den += p;
    }

    float inv = 1.f / (den + 1e-16f);
    float v0 = accx * inv + b1[2 * lane];
    float v1 = accy * inv + b1[2 * lane + 1];
    v0 = v0 > 0.f ? v0 : expm1f(v0);
    v1 = v1 > 0.f ? v1 : expm1f(v1);
    *(float2*)(g_f2 + (long long)d * 64 + 2 * lane) = make_float2(v0, v1);
}

// ---------------- layer-2 gather: warp per node, smem-staged (s,p), fused log_softmax (R8) ----------------
__global__ __launch_bounds__(256) void gather2_kernel(const float* __restrict__ b2,
                                                      float* __restrict__ out) {
    __shared__ uint2 s_sp[8][DEGCAP];   // (src, p) packed: one LDS.64 broadcast per edge

    const int warp = (blockIdx.x * 256 + threadIdx.x) >> 5;
    const int w    = (threadIdx.x >> 5);
    const int lane = threadIdx.x & 31;
    if (warp >= NNODES) return;
    const int d = warp;
    const unsigned FULL = 0xffffffffu;

    const float ad_d = g_ad2[d];

    int c = g_cnt[d];
    c = c > DEGCAP ? DEGCAP : c;
    const int* row = g_adj + d * DEGCAP;

    if (lane < c) {
        int e = row[lane];
        s_sp[w][lane] = make_uint2((unsigned)e, __float_as_uint(pe(g_as2[e] + ad_d)));
    }
    if (lane + 32 < c) {
        int e = row[lane + 32];
        s_sp[w][lane + 32] = make_uint2((unsigned)e, __float_as_uint(pe(g_as2[e] + ad_d)));
    }

    float accx, accy, den;
    {   // self-loop
        float p = pe(g_as2[d] + ad_d);
        float2 hv = *(const float2*)(g_h2 + (long long)d * 64 + 2 * lane);
        accx = hv.x * p; accy = hv.y * p; den = p;
    }
    __syncwarp();

    const float* hbase = g_h2 + 2 * lane;
    #pragma unroll 4
    for (int j = 0; j < c; j++) {
        uint2 sp = s_sp[w][j];               // LDS.64 broadcast
        int   sj = (int)sp.x;
        float p  = __uint_as_float(sp.y);
        float2 hv = *(const float2*)(hbase + (long long)sj * 64);
        accx = fmaf(hv.x, p, accx);
        accy = fmaf(hv.y, p, accy);
        den += p;
    }

    float inv = 1.f / (den + 1e-16f);
    float v0 = accx * inv + b2[2 * lane];
    float v1 = accy * inv + b2[2 * lane + 1];

    float mx = fmaxf(v0, v1);
    #pragma unroll
    for (int o = 16; o > 0; o >>= 1) mx = fmaxf(mx, __shfl_xor_sync(FULL, mx, o));
    float se = __expf(v0 - mx) + __expf(v1 - mx);
    #pragma unroll
    for (int o = 16; o > 0; o >>= 1) se += __shfl_xor_sync(FULL, se, o);
    float ls = mx + logf(se);

    *(float2*)(out + (long long)d * 64 + 2 * lane) = make_float2(v0 - ls, v1 - ls);
}

// ---------------- launch ----------------
extern "C" void kernel_launch(void* const* d_in, const int* in_sizes, int n_in,
                              void* d_out, int out_size) {
    const float* x      = (const float*)d_in[0];
    const int*   eidx   = (const int*)  d_in[1];
    const float* W1     = (const float*)d_in[2];
    const float* a_src1 = (const float*)d_in[3];
    const float* a_dst1 = (const float*)d_in[4];
    const float* b1     = (const float*)d_in[5];
    const float* W2     = (const float*)d_in[6];
    const float* a_src2 = (const float*)d_in[7];
    const float* a_dst2 = (const float*)d_in[8];
    const float* b2     = (const float*)d_in[9];
    float* out = (float*)d_out;

    const int* src = eidx;
    const int* dst = eidx + NEDGES;

    float *p_h1, *p_f2, *p_h2, *p_as1, *p_ad1, *p_as2, *p_ad2;
    int* p_cnt;
    cudaGetSymbolAddress((void**)&p_h1,  g_h1);
    cudaGetSymbolAddress((void**)&p_f2,  g_f2);
    cudaGetSymbolAddress((void**)&p_h2,  g_h2);
    cudaGetSymbolAddress((void**)&p_as1, g_as1);
    cudaGetSymbolAddress((void**)&p_ad1, g_ad1);
    cudaGetSymbolAddress((void**)&p_as2, g_as2);
    cudaGetSymbolAddress((void**)&p_ad2, g_ad2);
    cudaGetSymbolAddress((void**)&p_cnt, g_cnt);

    const int TB = 256;
    const int GB = (NNODES + 127) / 128;
    cudaMemsetAsync(p_cnt, 0, NNODES * sizeof(int));
    scatter_kernel<<<(NEDGES + TB - 1) / TB, TB>>>(src, dst);
    // layer 1 (alpha fused into gemm epilogue)
    gemm_kernel<FIN, true><<<GB, TB>>>(x, W1, p_h1, a_src1, a_dst1, p_as1, p_ad1);
    gather1_kernel<<<(NNODES * 32 + TB - 1) / TB, TB>>>(b1);
    // layer 2
    gemm_kernel<F1, false><<<GB, TB>>>(p_f2, W2, p_h2, a_src2, a_dst2, p_as2, p_ad2);
    gather2_kernel<<<(NNODES * 32 + TB - 1) / TB, TB>>>(b2, out);
}